// round 3
// baseline (speedup 1.0000x reference)
#include <cuda_runtime.h>
#include <math.h>

#define BG     256
#define NPG    512
#define EPG    8192
#define DF     128
#define CH     32
#define DFEAT  97
#define TOPK   64
#define NTH    1024
#define NW     32

#define BUF_STRIDE 33
#define SZ_BUF   (NPG*BUF_STRIDE)      // 16896 floats
#define SZ_WSM   4288
#define W0_STRIDE 132
#define W0_BIAS  (CH*W0_STRIDE)        // 4224
#define C1_BIAS  (16*97)               // 1552
#define C2W_OFF  1600                  // conv2 weights in Wsm
#define C2B_OFF  4160                  // conv2 bias in Wsm

// scratch: concat feature [N, 97]
__device__ float g_feat[(size_t)BG * NPG * DFEAT];

#define SMEM_FLOATS (2*SZ_BUF + SZ_WSM + NPG + NPG)        // bufA,bufB,Wsm,norm,key
#define SMEM_INTS   (NPG + (NPG+1) + NPG)                  // idx, row_off, tmp
#define SMEM_BYTES  (SMEM_FLOATS*4 + SMEM_INTS*4 + EPG*2)  // + csr (ushort)

__global__ void __launch_bounds__(NTH, 1)
dgcnn_kernel(const float* __restrict__ x,
             const float* __restrict__ W0, const float* __restrict__ b0,
             const float* __restrict__ W1, const float* __restrict__ b1,
             const float* __restrict__ W2, const float* __restrict__ b2,
             const float* __restrict__ W3, const float* __restrict__ b3,
             const float* __restrict__ c1w, const float* __restrict__ c1b,
             const float* __restrict__ c2w, const float* __restrict__ c2b,
             const float* __restrict__ d1w, const float* __restrict__ d1b,
             const float* __restrict__ d2w, const float* __restrict__ d2b,
             const int* __restrict__ esrc, const int* __restrict__ edst,
             float* __restrict__ out)
{
    extern __shared__ float sm[];
    float* bufA   = sm;
    float* bufB   = bufA + SZ_BUF;
    float* Wsm    = bufB + SZ_BUF;
    float* norm_s = Wsm + SZ_WSM;
    float* key_s  = norm_s + NPG;
    int*   idx_s  = (int*)(key_s + NPG);
    int*   row_off= idx_s + NPG;
    int*   tmp_i  = row_off + NPG + 1;
    unsigned short* csr = (unsigned short*)(tmp_i + NPG);

    const int g    = blockIdx.x;
    const int tid  = threadIdx.x;
    const int lane = tid & 31;
    const int wid  = tid >> 5;
    const int off  = g * NPG;
    const int* es  = esrc + g * EPG;
    const int* ed  = edst + g * EPG;

    // ================= degree counts (src for norm, dst for CSR) =============
    if (tid < NPG) { tmp_i[tid] = 0; idx_s[tid] = 0; }
    __syncthreads();
    for (int e = tid; e < EPG; e += NTH) {
        atomicAdd(&tmp_i[es[e] - off], 1);
        atomicAdd(&idx_s[ed[e] - off], 1);
    }
    __syncthreads();
    if (tid < NPG)
        norm_s[tid] = 1.0f / (float)(1 + tmp_i[tid]);   // +1 self loop
    __syncthreads();

    // exclusive scan of dst in-counts -> row_off (uniform barriers)
    {
        int dcnt = (tid < NPG) ? idx_s[tid] : 0;
        int v = dcnt;
        #pragma unroll
        for (int o = 1; o < 32; o <<= 1) {
            int nn = __shfl_up_sync(0xffffffffu, v, o);
            if (lane >= o) v += nn;
        }
        if (lane == 31) key_s[wid] = __int_as_float(v);   // key_s as scratch
        __syncthreads();
        if (wid == 0 && lane < 16) {
            int t = __float_as_int(key_s[lane]);
            int w = t;
            #pragma unroll
            for (int o = 1; o < 16; o <<= 1) {
                int nn = __shfl_up_sync(0x0000ffffu, w, o);
                if (lane >= o) w += nn;
            }
            key_s[lane] = __int_as_float(w - t);   // exclusive warp offset
        }
        __syncthreads();
        if (tid < NPG) {
            int ro = (v - dcnt) + __float_as_int(key_s[wid]);
            row_off[tid] = ro;
            tmp_i[tid] = ro;    // cursor
            if (tid == 0) row_off[NPG] = EPG;
        }
        __syncthreads();
    }

    // CSR fill (by dst; row order irrelevant — it's a sum)
    for (int e = tid; e < EPG; e += NTH) {
        int d = ed[e] - off;
        int p = atomicAdd(&tmp_i[d], 1);
        csr[p] = (unsigned short)(es[e] - off);
    }

    // ================= layer 0: lin = x @ W0^T + b0 ===========================
    for (int j = tid; j < CH * DF; j += NTH) {
        int r = j >> 7, c = j & 127;
        Wsm[r * W0_STRIDE + c] = W0[j];
    }
    if (tid < CH) Wsm[W0_BIAS + tid] = b0[tid];
    __syncthreads();

    {
        const float bias = Wsm[W0_BIAS + lane];
        const float* wr = Wsm + lane * W0_STRIDE;
        #pragma unroll 1
        for (int m = 0; m < 16; m += 4) {
            const int n0 = wid + 32 * m;
            const float* x0 = x + (size_t)(off + n0      ) * DF;
            const float* x1 = x + (size_t)(off + n0 + 32 ) * DF;
            const float* x2 = x + (size_t)(off + n0 + 64 ) * DF;
            const float* x3 = x + (size_t)(off + n0 + 96 ) * DF;
            float a0 = bias, a1 = bias, a2 = bias, a3 = bias;
            #pragma unroll 4
            for (int c = 0; c < DF; c += 4) {
                float4 wv = *(const float4*)(wr + c);
                float4 v0 = *(const float4*)(x0 + c);
                float4 v1 = *(const float4*)(x1 + c);
                float4 v2 = *(const float4*)(x2 + c);
                float4 v3 = *(const float4*)(x3 + c);
                a0 += v0.x*wv.x + v0.y*wv.y + v0.z*wv.z + v0.w*wv.w;
                a1 += v1.x*wv.x + v1.y*wv.y + v1.z*wv.z + v1.w*wv.w;
                a2 += v2.x*wv.x + v2.y*wv.y + v2.z*wv.z + v2.w*wv.w;
                a3 += v3.x*wv.x + v3.y*wv.y + v3.z*wv.z + v3.w*wv.w;
            }
            bufB[(n0      ) * BUF_STRIDE + lane] = a0;
            bufB[(n0 + 32 ) * BUF_STRIDE + lane] = a1;
            bufB[(n0 + 64 ) * BUF_STRIDE + lane] = a2;
            bufB[(n0 + 96 ) * BUF_STRIDE + lane] = a3;
        }
    }
    __syncthreads();

    // aggregate (32 channels): out[i] = tanh(norm[i]*(lin[i] + sum_in lin[src]))
    auto AGG32 = [&](const float* lin, float* ob, int fc) {
        for (int n = wid; n < NPG; n += NW) {
            float s = lin[n * BUF_STRIDE + lane];
            int e  = row_off[n];
            const int e1 = row_off[n + 1];
            float s2 = 0.0f, s3 = 0.0f, s4 = 0.0f;
            for (; e + 4 <= e1; e += 4) {
                int i0 = csr[e], i1 = csr[e+1], i2 = csr[e+2], i3 = csr[e+3];
                s  += lin[i0 * BUF_STRIDE + lane];
                s2 += lin[i1 * BUF_STRIDE + lane];
                s3 += lin[i2 * BUF_STRIDE + lane];
                s4 += lin[i3 * BUF_STRIDE + lane];
            }
            for (; e < e1; e++)
                s += lin[(int)csr[e] * BUF_STRIDE + lane];
            s += (s2 + s3) + s4;
            s = tanhf(s * norm_s[n]);
            ob[n * BUF_STRIDE + lane] = s;
            g_feat[(size_t)(off + n) * DFEAT + fc + lane] = s;
        }
        __syncthreads();
    };
    AGG32(bufB, bufA, 0);

    // ======== layers 1, 2 (32 -> 32): register weights + shfl broadcast ======
    #pragma unroll 1
    for (int L = 1; L <= 2; L++) {
        const float* Wg = (L == 1) ? W1 : W2;
        const float* bg = (L == 1) ? b1 : b2;

        float wreg[CH];
        #pragma unroll
        for (int c = 0; c < CH; c++) wreg[c] = __ldg(Wg + lane * CH + c);
        const float bias = __ldg(bg + lane);

        #pragma unroll 1
        for (int n = wid; n < NPG; n += NW) {
            float h = bufA[n * BUF_STRIDE + lane];
            float acc = bias;
            #pragma unroll
            for (int c = 0; c < CH; c++)
                acc += __shfl_sync(0xffffffffu, h, c) * wreg[c];
            bufB[n * BUF_STRIDE + lane] = acc;
        }
        __syncthreads();
        AGG32(bufB, bufA, 32 * L);
    }

    // ================= layer 3 (32 -> 1), key channel =========================
    if (tid < CH) Wsm[tid] = W3[tid];
    if (tid == 0) Wsm[CH] = b3[0];
    __syncthreads();
    if (tid < NPG) {
        const float* hr = bufA + tid * BUF_STRIDE;
        float acc = Wsm[CH];
        #pragma unroll
        for (int c = 0; c < CH; c++) acc += hr[c] * Wsm[c];
        bufB[tid * BUF_STRIDE] = acc;
    }
    __syncthreads();
    if (tid < NPG) {
        float s = bufB[tid * BUF_STRIDE];
        const int e1 = row_off[tid + 1];
        for (int e = row_off[tid]; e < e1; e++)
            s += bufB[(int)csr[e] * BUF_STRIDE];
        s = tanhf(s * norm_s[tid]);
        key_s[tid] = s;
        idx_s[tid] = tid;
        g_feat[(size_t)(off + tid) * DFEAT + 96] = s;
    }
    __syncthreads();

    // ================= bitonic sort: desc value, asc index (argsort match) ====
    for (int k = 2; k <= NPG; k <<= 1) {
        for (int j = k >> 1; j > 0; j >>= 1) {
            if (tid < NPG) {
                int ixj = tid ^ j;
                if (ixj > tid) {
                    float v0 = key_s[tid], v1 = key_s[ixj];
                    int   i0 = idx_s[tid], i1 = idx_s[ixj];
                    bool up = ((tid & k) == 0);
                    bool sw;
                    if (up) sw = (v1 > v0) || (v1 == v0 && i1 < i0);
                    else    sw = (v0 > v1) || (v0 == v1 && i0 < i1);
                    if (sw) {
                        key_s[tid] = v1; key_s[ixj] = v0;
                        idx_s[tid] = i1; idx_s[ixj] = i0;
                    }
                }
            }
            __syncthreads();
        }
    }

    // ================= gather top-K feature rows ==============================
    float* t64 = bufA;                 // 64*97
    for (int j = tid; j < TOPK * DFEAT; j += NTH) {
        int kk = j / DFEAT, d = j - kk * DFEAT;
        t64[j] = g_feat[(size_t)(off + idx_s[kk]) * DFEAT + d];
    }
    // conv1 + conv2 weights into smem
    for (int j = tid; j < 16 * 97; j += NTH) Wsm[j] = c1w[j];
    if (tid < 16) Wsm[C1_BIAS + tid] = c1b[tid];
    for (int j = tid; j < 32 * 16 * 5; j += NTH) Wsm[C2W_OFF + j] = c2w[j];
    if (tid < 32) Wsm[C2B_OFF + tid] = c2b[tid];
    __syncthreads();

    float* c1o  = bufB;          // 16*64
    float* pool = bufB + 1024;   // 16*32
    float* flat = bufB + 1664;   // 896
    float* hid  = bufB + 2600;   // 128

    // conv1 (per-node linear over D=97) + relu — exactly 1024 items
    {
        int o = tid >> 6, kk = tid & 63;
        const float* tr = t64 + kk * DFEAT;
        const float* wr = Wsm + o * DFEAT;
        float acc = Wsm[C1_BIAS + o];
        for (int d = 0; d < DFEAT; d++) acc += tr[d] * wr[d];
        c1o[tid] = fmaxf(acc, 0.0f);
    }
    __syncthreads();
    // maxpool(2)
    if (tid < 16 * 32) {
        int o = tid >> 5, j2 = tid & 31;
        pool[tid] = fmaxf(c1o[o * 64 + 2 * j2], c1o[o * 64 + 2 * j2 + 1]);
    }
    __syncthreads();
    // conv2 (16->32, k=5, valid) + relu, flat index = o*28 + t
    if (tid < 896) {
        int o = tid / 28, t = tid - o * 28;
        const float* wo = Wsm + C2W_OFF + o * 80;
        const float* pb = pool + t;
        float acc = Wsm[C2B_OFF + o];
        #pragma unroll
        for (int i = 0; i < 16; i++) {
            #pragma unroll
            for (int kk = 0; kk < 5; kk++)
                acc += pb[i * 32 + kk] * wo[i * 5 + kk];
        }
        flat[tid] = fmaxf(acc, 0.0f);
    }
    __syncthreads();

    // dense 896 -> 128, relu  (warp per output row, strided lanes, shfl reduce)
    for (int h = wid; h < 128; h += NW) {
        const float* wr = d1w + (size_t)h * 896;
        float acc = 0.0f;
        for (int m = lane; m < 896; m += 32) acc += flat[m] * wr[m];
        #pragma unroll
        for (int o = 16; o > 0; o >>= 1) acc += __shfl_down_sync(0xffffffffu, acc, o);
        if (lane == 0) hid[h] = fmaxf(acc + d1b[h], 0.0f);
    }
    __syncthreads();

    // dense 128 -> 10
    if (wid < 10) {
        const float* wr = d2w + wid * 128;
        float acc = 0.0f;
        for (int m = lane; m < 128; m += 32) acc += hid[m] * wr[m];
        #pragma unroll
        for (int o = 16; o > 0; o >>= 1) acc += __shfl_down_sync(0xffffffffu, acc, o);
        if (lane == 0) out[g * 10 + wid] = acc + d2b[wid];
    }
}

extern "C" void kernel_launch(void* const* d_in, const int* in_sizes, int n_in,
                              void* d_out, int out_size)
{
    (void)in_sizes; (void)n_in; (void)out_size;
    const float* x    = (const float*)d_in[0];
    const float* W0   = (const float*)d_in[1];
    const float* b0   = (const float*)d_in[2];
    const float* W1   = (const float*)d_in[3];
    const float* b1   = (const float*)d_in[4];
    const float* W2   = (const float*)d_in[5];
    const float* b2   = (const float*)d_in[6];
    const float* W3   = (const float*)d_in[7];
    const float* b3   = (const float*)d_in[8];
    const float* c1w  = (const float*)d_in[9];
    const float* c1b  = (const float*)d_in[10];
    const float* c2w  = (const float*)d_in[11];
    const float* c2b  = (const float*)d_in[12];
    const float* d1w  = (const float*)d_in[13];
    const float* d1b  = (const float*)d_in[14];
    const float* d2w  = (const float*)d_in[15];
    const float* d2b  = (const float*)d_in[16];
    const int*   esrc = (const int*)d_in[17];
    const int*   edst = (const int*)d_in[18];
    float* out = (float*)d_out;

    cudaFuncSetAttribute(dgcnn_kernel,
                         cudaFuncAttributeMaxDynamicSharedMemorySize, SMEM_BYTES);
    dgcnn_kernel<<<BG, NTH, SMEM_BYTES>>>(x, W0, b0, W1, b1, W2, b2, W3, b3,
                                          c1w, c1b, c2w, c2b,
                                          d1w, d1b, d2w, d2b,
                                          esrc, edst, out);
}

// round 4
// speedup vs baseline: 1.2276x; 1.2276x over previous
#include <cuda_runtime.h>
#include <math.h>

#define BG     256
#define NPG    512
#define EPG    8192
#define DF     128
#define CH     32
#define DFEAT  97
#define TOPK   64
#define NTH    512
#define NW     16

#define BUF_STRIDE 33
#define SZ_BUF   (NPG*BUF_STRIDE)      // 16896 floats (single lin buffer)
#define SZ_WSM   4288
#define W0_STRIDE 132
#define W0_BIAS  (CH*W0_STRIDE)        // 4224
#define W12_BIAS (CH*33)               // 1056
#define C1_BIAS  (16*97)               // 1552
#define C2W_OFF  1600
#define C2B_OFF  4160

// scratch: concat feature [N, 97]
__device__ float g_feat[(size_t)BG * NPG * DFEAT];

#define SMEM_FLOATS (SZ_BUF + SZ_WSM + NPG + NPG)          // bufL, Wsm, norm, key
#define SMEM_INTS   (NPG + (NPG+1) + NPG)                  // idx, row_off, tmp
#define SMEM_BYTES  (SMEM_FLOATS*4 + SMEM_INTS*4 + EPG*2)  // + csr (ushort) = 111364

__global__ void __launch_bounds__(NTH, 2)
dgcnn_kernel(const float* __restrict__ x,
             const float* __restrict__ W0, const float* __restrict__ b0,
             const float* __restrict__ W1, const float* __restrict__ b1,
             const float* __restrict__ W2, const float* __restrict__ b2,
             const float* __restrict__ W3, const float* __restrict__ b3,
             const float* __restrict__ c1w, const float* __restrict__ c1b,
             const float* __restrict__ c2w, const float* __restrict__ c2b,
             const float* __restrict__ d1w, const float* __restrict__ d1b,
             const float* __restrict__ d2w, const float* __restrict__ d2b,
             const int* __restrict__ esrc, const int* __restrict__ edst,
             float* __restrict__ out)
{
    extern __shared__ float sm[];
    float* bufL   = sm;                      // [512][33] lin scratch
    float* Wsm    = bufL + SZ_BUF;
    float* norm_s = Wsm + SZ_WSM;
    float* key_s  = norm_s + NPG;
    int*   idx_s  = (int*)(key_s + NPG);
    int*   row_off= idx_s + NPG;
    int*   tmp_i  = row_off + NPG + 1;
    unsigned short* csr = (unsigned short*)(tmp_i + NPG);
    float* lin3_s = (float*)tmp_i;           // reuse after CSR fill

    const int g    = blockIdx.x;
    const int tid  = threadIdx.x;
    const int lane = tid & 31;
    const int wid  = tid >> 5;
    const int off  = g * NPG;
    const int* es  = esrc + g * EPG;
    const int* ed  = edst + g * EPG;
    float* gf = g_feat + (size_t)off * DFEAT;

    // ================= degree counts (src for norm, dst for CSR) =============
    tmp_i[tid] = 0;
    idx_s[tid] = 0;
    __syncthreads();
    for (int e = tid; e < EPG; e += NTH) {
        atomicAdd(&tmp_i[es[e] - off], 1);
        atomicAdd(&idx_s[ed[e] - off], 1);
    }
    __syncthreads();
    norm_s[tid] = 1.0f / (float)(1 + tmp_i[tid]);   // +1 self loop
    const int dcnt = idx_s[tid];
    __syncthreads();

    // exclusive scan of dst in-counts -> row_off
    {
        int v = dcnt;
        #pragma unroll
        for (int o = 1; o < 32; o <<= 1) {
            int nn = __shfl_up_sync(0xffffffffu, v, o);
            if (lane >= o) v += nn;
        }
        if (lane == 31) key_s[wid] = __int_as_float(v);
        __syncthreads();
        if (wid == 0 && lane < NW) {
            int t = __float_as_int(key_s[lane]);
            int w = t;
            #pragma unroll
            for (int o = 1; o < NW; o <<= 1) {
                int nn = __shfl_up_sync(0x0000ffffu, w, o);
                if (lane >= o) w += nn;
            }
            key_s[lane] = __int_as_float(w - t);
        }
        __syncthreads();
        int ro = (v - dcnt) + __float_as_int(key_s[wid]);
        row_off[tid] = ro;
        tmp_i[tid] = ro;                    // cursor
        if (tid == 0) row_off[NPG] = EPG;
        __syncthreads();
    }

    // CSR fill (by dst; row order irrelevant — it's a sum)
    for (int e = tid; e < EPG; e += NTH) {
        int d = ed[e] - off;
        int p = atomicAdd(&tmp_i[d], 1);
        csr[p] = (unsigned short)(es[e] - off);
    }

    // ================= layer 0: lin = x @ W0^T + b0 ===========================
    for (int j = tid; j < CH * DF; j += NTH) {
        int r = j >> 7, c = j & 127;
        Wsm[r * W0_STRIDE + c] = W0[j];
    }
    if (tid < CH) Wsm[W0_BIAS + tid] = b0[tid];
    __syncthreads();

    {
        const float bias = Wsm[W0_BIAS + lane];
        const float* wr = Wsm + lane * W0_STRIDE;
        #pragma unroll 1
        for (int m = 0; m < 8; m++) {
            const int n0 = m * 64 + wid * 4;
            const float* x0 = x + (size_t)(off + n0    ) * DF;
            const float* x1 = x + (size_t)(off + n0 + 1) * DF;
            const float* x2 = x + (size_t)(off + n0 + 2) * DF;
            const float* x3 = x + (size_t)(off + n0 + 3) * DF;
            float a0 = bias, a1 = bias, a2 = bias, a3 = bias;
            #pragma unroll 4
            for (int c = 0; c < DF; c += 4) {
                float4 wv = *(const float4*)(wr + c);
                float4 v0 = *(const float4*)(x0 + c);
                float4 v1 = *(const float4*)(x1 + c);
                float4 v2 = *(const float4*)(x2 + c);
                float4 v3 = *(const float4*)(x3 + c);
                a0 += v0.x*wv.x + v0.y*wv.y + v0.z*wv.z + v0.w*wv.w;
                a1 += v1.x*wv.x + v1.y*wv.y + v1.z*wv.z + v1.w*wv.w;
                a2 += v2.x*wv.x + v2.y*wv.y + v2.z*wv.z + v2.w*wv.w;
                a3 += v3.x*wv.x + v3.y*wv.y + v3.z*wv.z + v3.w*wv.w;
            }
            bufL[(n0    ) * BUF_STRIDE + lane] = a0;
            bufL[(n0 + 1) * BUF_STRIDE + lane] = a1;
            bufL[(n0 + 2) * BUF_STRIDE + lane] = a2;
            bufL[(n0 + 3) * BUF_STRIDE + lane] = a3;
        }
    }
    __syncthreads();

    // aggregate: h[i] = tanh(norm[i]*(lin[i]+sum lin[src])) -> g_feat only
    auto AGG32 = [&](int fc) {
        for (int n = wid; n < NPG; n += NW) {
            float s = bufL[n * BUF_STRIDE + lane];
            int e  = row_off[n];
            const int e1 = row_off[n + 1];
            float s2 = 0.0f, s3 = 0.0f, s4 = 0.0f;
            for (; e + 4 <= e1; e += 4) {
                int i0 = csr[e], i1 = csr[e+1], i2 = csr[e+2], i3 = csr[e+3];
                s  += bufL[i0 * BUF_STRIDE + lane];
                s2 += bufL[i1 * BUF_STRIDE + lane];
                s3 += bufL[i2 * BUF_STRIDE + lane];
                s4 += bufL[i3 * BUF_STRIDE + lane];
            }
            for (; e < e1; e++)
                s += bufL[(int)csr[e] * BUF_STRIDE + lane];
            s += (s2 + s3) + s4;
            s = tanhf(s * norm_s[n]);
            gf[(size_t)n * DFEAT + fc + lane] = s;
        }
        __syncthreads();
    };
    AGG32(0);

    // ========== layers 1, 2 (32->32): h from g_feat, weights in smem =========
    #pragma unroll 1
    for (int L = 1; L <= 2; L++) {
        const float* Wg = (L == 1) ? W1 : W2;
        const float* bg = (L == 1) ? b1 : b2;
        const int fcin = 32 * (L - 1);
        for (int j = tid; j < CH * CH; j += NTH) {
            int r = j >> 5, c = j & 31;
            Wsm[r * 33 + c] = Wg[j];
        }
        if (tid < CH) Wsm[W12_BIAS + tid] = bg[tid];
        __syncthreads();

        const float bias = Wsm[W12_BIAS + lane];
        const float* wr = Wsm + lane * 33;
        #pragma unroll 1
        for (int m = 0; m < 8; m++) {
            const int n0 = m * 64 + wid * 4;
            const float* h0 = gf + (size_t)(n0    ) * DFEAT + fcin;
            const float* h1 = gf + (size_t)(n0 + 1) * DFEAT + fcin;
            const float* h2 = gf + (size_t)(n0 + 2) * DFEAT + fcin;
            const float* h3 = gf + (size_t)(n0 + 3) * DFEAT + fcin;
            float a0 = bias, a1 = bias, a2 = bias, a3 = bias;
            #pragma unroll
            for (int c = 0; c < CH; c++) {
                float wv = wr[c];
                a0 += __ldg(h0 + c) * wv;
                a1 += __ldg(h1 + c) * wv;
                a2 += __ldg(h2 + c) * wv;
                a3 += __ldg(h3 + c) * wv;
            }
            bufL[(n0    ) * BUF_STRIDE + lane] = a0;
            bufL[(n0 + 1) * BUF_STRIDE + lane] = a1;
            bufL[(n0 + 2) * BUF_STRIDE + lane] = a2;
            bufL[(n0 + 3) * BUF_STRIDE + lane] = a3;
        }
        __syncthreads();
        AGG32(32 * L);
    }

    // ============== layer 3 (32 -> 1): warp-per-node, shfl reduce =============
    {
        const float w3v = __ldg(W3 + lane);
        const float b3v = __ldg(b3);
        for (int i = 0; i < NPG / NW; i++) {
            const int n = wid * (NPG / NW) + i;
            float acc = gf[(size_t)n * DFEAT + 64 + lane] * w3v;
            #pragma unroll
            for (int o = 16; o > 0; o >>= 1)
                acc += __shfl_down_sync(0xffffffffu, acc, o);
            if (lane == 0) lin3_s[n] = acc + b3v;
        }
    }
    __syncthreads();

    // key aggregation (per-thread node)
    {
        float s = lin3_s[tid];
        const int e1 = row_off[tid + 1];
        for (int e = row_off[tid]; e < e1; e++)
            s += lin3_s[(int)csr[e]];
        s = tanhf(s * norm_s[tid]);
        key_s[tid] = s;
        idx_s[tid] = tid;
        gf[(size_t)tid * DFEAT + 96] = s;
    }
    __syncthreads();

    // ============ bitonic sort: desc value, asc index (argsort match) =========
    for (int k = 2; k <= NPG; k <<= 1) {
        for (int j = k >> 1; j > 0; j >>= 1) {
            int ixj = tid ^ j;
            if (ixj > tid) {
                float v0 = key_s[tid], v1 = key_s[ixj];
                int   i0 = idx_s[tid], i1 = idx_s[ixj];
                bool up = ((tid & k) == 0);
                bool sw;
                if (up) sw = (v1 > v0) || (v1 == v0 && i1 < i0);
                else    sw = (v0 > v1) || (v0 == v1 && i0 < i1);
                if (sw) {
                    key_s[tid] = v1; key_s[ixj] = v0;
                    idx_s[tid] = i1; idx_s[ixj] = i0;
                }
            }
            __syncthreads();
        }
    }

    // ================= gather top-K feature rows ==============================
    float* t64 = bufL;                 // 64*97 = 6208 floats
    for (int j = tid; j < TOPK * DFEAT; j += NTH) {
        int kk = j / DFEAT, d = j - kk * DFEAT;
        t64[j] = gf[(size_t)idx_s[kk] * DFEAT + d];
    }
    for (int j = tid; j < 16 * 97; j += NTH) Wsm[j] = c1w[j];
    if (tid < 16) Wsm[C1_BIAS + tid] = c1b[tid];
    for (int j = tid; j < 32 * 16 * 5; j += NTH) Wsm[C2W_OFF + j] = c2w[j];
    if (tid < 32) Wsm[C2B_OFF + tid] = c2b[tid];
    __syncthreads();

    float* c1o  = bufL + 6208;   // 1024
    float* pool = bufL + 7232;   // 512
    float* flat = bufL + 7744;   // 896
    float* hid  = bufL + 8640;   // 128

    // conv1 (per-node linear over D=97) + relu — 1024 items, 2 per thread
    #pragma unroll
    for (int it = 0; it < 2; it++) {
        int j = tid + it * NTH;
        int o = j >> 6, kk = j & 63;
        const float* tr = t64 + kk * DFEAT;
        const float* wr = Wsm + o * DFEAT;
        float acc = Wsm[C1_BIAS + o];
        for (int d = 0; d < DFEAT; d++) acc += tr[d] * wr[d];
        c1o[j] = fmaxf(acc, 0.0f);
    }
    __syncthreads();
    // maxpool(2)
    if (tid < 16 * 32) {
        int o = tid >> 5, j2 = tid & 31;
        pool[tid] = fmaxf(c1o[o * 64 + 2 * j2], c1o[o * 64 + 2 * j2 + 1]);
    }
    __syncthreads();
    // conv2 (16->32, k=5, valid) + relu, flat index = o*28 + t
    #pragma unroll
    for (int it = 0; it < 2; it++) {
        int j = tid + it * NTH;
        if (j < 896) {
            int o = j / 28, t = j - o * 28;
            const float* wo = Wsm + C2W_OFF + o * 80;
            const float* pb = pool + t;
            float acc = Wsm[C2B_OFF + o];
            #pragma unroll
            for (int i = 0; i < 16; i++) {
                #pragma unroll
                for (int kk = 0; kk < 5; kk++)
                    acc += pb[i * 32 + kk] * wo[i * 5 + kk];
            }
            flat[j] = fmaxf(acc, 0.0f);
        }
    }
    __syncthreads();

    // dense 896 -> 128, relu  (warp per output row)
    for (int h = wid; h < 128; h += NW) {
        const float* wr = d1w + (size_t)h * 896;
        float acc = 0.0f;
        for (int m = lane; m < 896; m += 32) acc += flat[m] * wr[m];
        #pragma unroll
        for (int o = 16; o > 0; o >>= 1) acc += __shfl_down_sync(0xffffffffu, acc, o);
        if (lane == 0) hid[h] = fmaxf(acc + d1b[h], 0.0f);
    }
    __syncthreads();

    // dense 128 -> 10
    if (wid < 10) {
        const float* wr = d2w + wid * 128;
        float acc = 0.0f;
        for (int m = lane; m < 128; m += 32) acc += hid[m] * wr[m];
        #pragma unroll
        for (int o = 16; o > 0; o >>= 1) acc += __shfl_down_sync(0xffffffffu, acc, o);
        if (lane == 0) out[g * 10 + wid] = acc + d2b[wid];
    }
}

extern "C" void kernel_launch(void* const* d_in, const int* in_sizes, int n_in,
                              void* d_out, int out_size)
{
    (void)in_sizes; (void)n_in; (void)out_size;
    const float* x    = (const float*)d_in[0];
    const float* W0   = (const float*)d_in[1];
    const float* b0   = (const float*)d_in[2];
    const float* W1   = (const float*)d_in[3];
    const float* b1   = (const float*)d_in[4];
    const float* W2   = (const float*)d_in[5];
    const float* b2   = (const float*)d_in[6];
    const float* W3   = (const float*)d_in[7];
    const float* b3   = (const float*)d_in[8];
    const float* c1w  = (const float*)d_in[9];
    const float* c1b  = (const float*)d_in[10];
    const float* c2w  = (const float*)d_in[11];
    const float* c2b  = (const float*)d_in[12];
    const float* d1w  = (const float*)d_in[13];
    const float* d1b  = (const float*)d_in[14];
    const float* d2w  = (const float*)d_in[15];
    const float* d2b  = (const float*)d_in[16];
    const int*   esrc = (const int*)d_in[17];
    const int*   edst = (const int*)d_in[18];
    float* out = (float*)d_out;

    cudaFuncSetAttribute(dgcnn_kernel,
                         cudaFuncAttributeMaxDynamicSharedMemorySize, SMEM_BYTES);
    dgcnn_kernel<<<BG, NTH, SMEM_BYTES>>>(x, W0, b0, W1, b1, W2, b2, W3, b3,
                                          c1w, c1b, c2w, c2b,
                                          d1w, d1b, d2w, d2b,
                                          esrc, edst, out);
}